// round 14
// baseline (speedup 1.0000x reference)
#include <cuda_runtime.h>
#include <cstdint>

// Problem constants (fixed shapes): x = (8,32,256,256) fp32, K=3
#define PLANES 256            // B*C
#define H      256
#define W      256
#define HO     254
#define WO     254
#define N_ELEM (PLANES * H * W)     // 16,777,216
#define N32    (N_ELEM / 8)         // 32-byte units

// Hist config
#define HB 1024
#define HTH 256
#define HITER8 (N32 / (HB * HTH))   // 8 x 32-byte loads per thread (64 elems)

// Pool config
#define PTH 32                // output rows per block
#define PROWS (PTH + 2)       // input rows per block (34)
#define WP16 264              // u16 tile row stride: 528 B = 33*16 (STS.128-aligned)

typedef unsigned long long ull;

// bin i lives at g_cnt_pad[i*32] (128 B stride -> spread across LTS slices).
// Zero-init at load; zeroed again by the last hist block each replay.
__device__ unsigned int g_cnt_pad[256 * 32];
__device__ unsigned int g_packed[256];   // key16=(rank<<8|value) duplicated in both halves
__device__ unsigned int g_ticket;

// ---------------------------------------------------------------------------
// Kernel 1: 256-bin histogram, 16-bit packed shared counters (2 bins/word),
// bank == lane -> zero conflicts (~92% of the 4 ATOMS/cyc/SM floor).
// Tail: ticket via atom.acq_rel (NO threadfence - the R12 MEMBAR.GPU on all
// threads cost ~6us). bar.sync orders each block's REDs before its release-
// RMW; the last block's acq_rel RMW synchronizes with the whole release
// chain, so its reads see all REDs. Last block computes the RANK transform
// (rank = #{u: cnt[u]<cnt[v]}, exact-tie preserving, 8 bits) into g_packed
// (duplicated halves for PRMT packing in pool) and resets scratch+ticket.
// ---------------------------------------------------------------------------
__global__ void __launch_bounds__(HTH) hist_kernel(const float* __restrict__ x) {
    __shared__ unsigned int s_h[128 * 32];   // 16 KB
    __shared__ unsigned s_last;
    const int tid = threadIdx.x;
    #pragma unroll
    for (int i = tid; i < 128 * 32; i += HTH) s_h[i] = 0u;
    __syncthreads();

    const int lane = tid & 31;
    const ull* base = (const ull*)x + (size_t)blockIdx.x * (HTH * HITER8) * 4;

    #pragma unroll
    for (int j = 0; j < HITER8; j++) {
        ull u0, u1, u2, u3;
        const ull* p = base + (size_t)(j * HTH + tid) * 4;
        asm volatile("ld.global.nc.L2::evict_last.v4.b64 {%0,%1,%2,%3}, [%4];"
                     : "=l"(u0), "=l"(u1), "=l"(u2), "=l"(u3) : "l"(p));
        #pragma unroll
        for (int q = 0; q < 4; q++) {
            ull u = (q == 0) ? u0 : (q == 1) ? u1 : (q == 2) ? u2 : u3;
            int a = ((int)__uint_as_float((unsigned)u)) & 255;
            int b = ((int)__uint_as_float((unsigned)(u >> 32))) & 255;
            atomicAdd(&s_h[(a >> 1) * 32 + lane], 1u << ((a & 1) << 4));
            atomicAdd(&s_h[(b >> 1) * 32 + lane], 1u << ((b & 1) << 4));
        }
    }
    __syncthreads();

    if (tid < 128) {
        unsigned lo = 0, hi = 0;
        #pragma unroll
        for (int j = 0; j < 32; j++) {
            unsigned w = s_h[tid * 32 + ((j + lane) & 31)];
            lo += w & 0xFFFFu;
            hi += w >> 16;
        }
        atomicAdd(&g_cnt_pad[(2 * tid + 0) * 32], lo);   // RED, no return
        atomicAdd(&g_cnt_pad[(2 * tid + 1) * 32], hi);
    }

    // --- last-block tail (fence-free ticket) ---
    __syncthreads();                      // orders this block's REDs
    if (tid == 0) {
        unsigned old;
        asm volatile("atom.acq_rel.gpu.global.add.u32 %0, [%1], %2;"
                     : "=r"(old) : "l"(&g_ticket), "r"(1u) : "memory");
        s_last = (old == (unsigned)(HB - 1)) ? 1u : 0u;
    }
    __syncthreads();
    if (s_last) {
        unsigned cnt = __ldcg(&g_cnt_pad[tid * 32]);
        s_h[tid] = cnt;                   // reuse smem as count table
        __syncthreads();
        unsigned r = 0;
        #pragma unroll 8
        for (int j = 0; j < 256; j++) r += (s_h[j] < cnt) ? 1u : 0u;
        unsigned key = (r << 8) | (unsigned)tid;
        g_packed[tid] = key | (key << 16);
        g_cnt_pad[tid * 32] = 0u;
        if (tid == 0) g_ticket = 0u;
    }
}

// ---------------------------------------------------------------------------
// Kernel 2: entropy pool, full-width 32-row strips, u16 rank-packed tile.
// Phase 1: 32-byte ld.global.nc.v4.b64 (x is L2-resident from hist), 8 table
//          lookups (entries key|key<<16), 4 PRMT -> uint4 STS.128.
// Phase 2: thread = (rg in {0,1} x 16 rows, cg = column pair 2cg,2cg+1).
//          Per input row: 2 x LDS.32 -> 4 u16 -> both horizontal 3-mins with
//          pre-extracted ranks; rolling vertical 3-min compares the stored
//          ranks only (no per-compare shifts). Strict '<' in row-then-col
//          order == jnp.argmin first-occurrence (equal counts -> equal rank).
//          Stores: contiguous float2. Pad cols 256..263 are garbage but feed
//          only discarded outputs (cg=127 returns; col 253 uses cols<=255).
// ---------------------------------------------------------------------------
__global__ void __launch_bounds__(256) pool_kernel(const float* __restrict__ x,
                                                   float* __restrict__ out) {
    __shared__ unsigned s_tbl[256];
    __shared__ unsigned short s16[PROWS * WP16];   // 17,952 B

    const int tid = threadIdx.x;
    s_tbl[tid] = g_packed[tid];
    __syncthreads();

    const int plane = blockIdx.y;
    const int r0 = blockIdx.x * PTH;
    const int nout = min(PTH, HO - r0);
    const int rows_in = nout + 2;

    const ull* bp = (const ull*)(x + (size_t)plane * (H * W)) + (size_t)r0 * (W / 2);
    const int n8 = rows_in * 32;          // 32-byte units in the strip

    for (int i = tid; i < n8; i += 256) {
        ull u0, u1, u2, u3;
        const ull* p = bp + (size_t)i * 4;
        asm volatile("ld.global.nc.v4.b64 {%0,%1,%2,%3}, [%4];"
                     : "=l"(u0), "=l"(u1), "=l"(u2), "=l"(u3) : "l"(p));
        unsigned e0 = s_tbl[((int)__uint_as_float((unsigned)u0)) & 255];
        unsigned e1 = s_tbl[((int)__uint_as_float((unsigned)(u0 >> 32))) & 255];
        unsigned e2 = s_tbl[((int)__uint_as_float((unsigned)u1)) & 255];
        unsigned e3 = s_tbl[((int)__uint_as_float((unsigned)(u1 >> 32))) & 255];
        unsigned e4 = s_tbl[((int)__uint_as_float((unsigned)u2)) & 255];
        unsigned e5 = s_tbl[((int)__uint_as_float((unsigned)(u2 >> 32))) & 255];
        unsigned e6 = s_tbl[((int)__uint_as_float((unsigned)u3)) & 255];
        unsigned e7 = s_tbl[((int)__uint_as_float((unsigned)(u3 >> 32))) & 255];
        uint4 pk;
        pk.x = __byte_perm(e0, e1, 0x5410);
        pk.y = __byte_perm(e2, e3, 0x5410);
        pk.z = __byte_perm(e4, e5, 0x5410);
        pk.w = __byte_perm(e6, e7, 0x5410);
        const int row = i >> 5, c8 = (i & 31) * 8;
        *(uint4*)&s16[row * WP16 + c8] = pk;
    }
    __syncthreads();

    const int cg = tid & 127;        // column pair: cols 2cg, 2cg+1
    const int rg = tid >> 7;         // 0/1 -> out rows 16rg..16rg+15
    const int c0 = 2 * cg;
    const int lr0 = rg * 16;

    if (c0 >= WO) return;            // cg==127: cols 254,255 both invalid

    unsigned k0[3], k1[3], r0a[3], r1a[3];

    auto hrow = [&](int lr, int s) {
        unsigned A = *(const unsigned*)&s16[lr * WP16 + c0];      // cols c0,c0+1
        unsigned B = *(const unsigned*)&s16[lr * WP16 + c0 + 2];  // cols c0+2,c0+3
        unsigned w0 = A & 0xFFFFu, w1 = A >> 16;
        unsigned w2 = B & 0xFFFFu, w3 = B >> 16;
        unsigned t;
        unsigned q0 = w0, qr0 = w0 >> 8;
        t = w1 >> 8; if (t < qr0) { qr0 = t; q0 = w1; }
        t = w2 >> 8; if (t < qr0) { qr0 = t; q0 = w2; }
        unsigned q1 = w1, qr1 = w1 >> 8;
        t = w2 >> 8; if (t < qr1) { qr1 = t; q1 = w2; }
        t = w3 >> 8; if (t < qr1) { qr1 = t; q1 = w3; }
        k0[s] = q0; r0a[s] = qr0;
        k1[s] = q1; r1a[s] = qr1;
    };

    hrow(lr0 + 0, 0);
    hrow(lr0 + 1, 1);

    float* op = out + (size_t)plane * (HO * WO);
    #pragma unroll
    for (int k = 0; k < 16; k++) {
        const int orow = r0 + lr0 + k;
        if (orow >= HO) break;
        hrow(lr0 + k + 2, (k + 2) % 3);
        const int i0 = k % 3, i1 = (k + 1) % 3, i2 = (k + 2) % 3;
        unsigned q0 = k0[i0], qr0 = r0a[i0];
        if (r0a[i1] < qr0) { qr0 = r0a[i1]; q0 = k0[i1]; }
        if (r0a[i2] < qr0) { qr0 = r0a[i2]; q0 = k0[i2]; }
        unsigned q1 = k1[i0], qr1 = r1a[i0];
        if (r1a[i1] < qr1) { qr1 = r1a[i1]; q1 = k1[i1]; }
        if (r1a[i2] < qr1) { qr1 = r1a[i2]; q1 = k1[i2]; }
        float2 o;
        o.x = (float)(q0 & 0xFFu);
        o.y = (float)(q1 & 0xFFu);
        __stcs((float2*)&op[(size_t)orow * WO + c0], o);
    }
}

// ---------------------------------------------------------------------------
extern "C" void kernel_launch(void* const* d_in, const int* in_sizes, int n_in,
                              void* d_out, int out_size) {
    const float* x = (const float*)d_in[0];
    float* out = (float*)d_out;

    hist_kernel<<<HB, HTH>>>(x);

    dim3 grid((HO + PTH - 1) / PTH, PLANES);   // (8, 256) = 2048 blocks
    pool_kernel<<<grid, 256>>>(x, out);
}

// round 17
// speedup vs baseline: 1.0462x; 1.0462x over previous
#include <cuda_runtime.h>
#include <cstdint>

// Problem constants (fixed shapes): x = (8,32,256,256) fp32, K=3
#define PLANES 256            // B*C
#define H      256
#define W      256
#define HO     254
#define WO     254
#define N_ELEM (PLANES * H * W)     // 16,777,216
#define N32    (N_ELEM / 8)         // 32-byte units

// Hist config
#define HB 1024
#define HTH 256
#define HITER8 (N32 / (HB * HTH))   // 8 x 32-byte loads per thread (64 elems)

// Pool config: 14 output rows per block -> 16 input rows -> phase 1 is exactly
// 512 x 32-byte units = 2 fixed iterations of 256 threads.
#define PTH 14
#define PROWS 16
#define WPAD 260              // u32 tile row stride (1040 B = 65*16, STS.128-aligned)

typedef unsigned long long ull;

// bin i lives at g_cnt_pad[i*32] (128 B stride -> spread across LTS slices).
// Zero-init at load; zeroed again by the last hist block each replay.
__device__ unsigned int g_cnt_pad[256 * 32];
__device__ unsigned int g_packed[256];   // (rank<<24) | value
__device__ unsigned int g_ticket;

// ---------------------------------------------------------------------------
// Kernel 1: 256-bin histogram, 16-bit packed shared counters (2 bins/word),
// bank == lane -> zero conflicts (~92% of the 4 ATOMS/cyc/SM floor).
// Tail: fence-free ticket (bar.sync orders this block's REDs before its
// release-RMW; last block's acq_rel RMW syncs with the whole release chain).
// Last block computes the RANK transform (rank = #{u: cnt[u]<cnt[v]},
// exact-tie preserving) into g_packed as (rank<<24)|value, resets scratch.
// ---------------------------------------------------------------------------
__global__ void __launch_bounds__(HTH) hist_kernel(const float* __restrict__ x) {
    __shared__ unsigned int s_h[128 * 32];   // 16 KB
    __shared__ unsigned s_last;
    const int tid = threadIdx.x;
    #pragma unroll
    for (int i = tid; i < 128 * 32; i += HTH) s_h[i] = 0u;
    __syncthreads();

    const int lane = tid & 31;
    const ull* base = (const ull*)x + (size_t)blockIdx.x * (HTH * HITER8) * 4;

    #pragma unroll
    for (int j = 0; j < HITER8; j++) {
        ull u0, u1, u2, u3;
        const ull* p = base + (size_t)(j * HTH + tid) * 4;
        asm volatile("ld.global.nc.L2::evict_last.v4.b64 {%0,%1,%2,%3}, [%4];"
                     : "=l"(u0), "=l"(u1), "=l"(u2), "=l"(u3) : "l"(p));
        #pragma unroll
        for (int q = 0; q < 4; q++) {
            ull u = (q == 0) ? u0 : (q == 1) ? u1 : (q == 2) ? u2 : u3;
            int a = ((int)__uint_as_float((unsigned)u)) & 255;
            int b = ((int)__uint_as_float((unsigned)(u >> 32))) & 255;
            atomicAdd(&s_h[(a >> 1) * 32 + lane], 1u << ((a & 1) << 4));
            atomicAdd(&s_h[(b >> 1) * 32 + lane], 1u << ((b & 1) << 4));
        }
    }
    __syncthreads();

    if (tid < 128) {
        unsigned lo = 0, hi = 0;
        #pragma unroll
        for (int j = 0; j < 32; j++) {
            unsigned w = s_h[tid * 32 + ((j + lane) & 31)];
            lo += w & 0xFFFFu;
            hi += w >> 16;
        }
        atomicAdd(&g_cnt_pad[(2 * tid + 0) * 32], lo);   // RED, no return
        atomicAdd(&g_cnt_pad[(2 * tid + 1) * 32], hi);
    }

    // --- last-block tail (fence-free ticket) ---
    __syncthreads();                      // orders this block's REDs
    if (tid == 0) {
        unsigned old;
        asm volatile("atom.acq_rel.gpu.global.add.u32 %0, [%1], %2;"
                     : "=r"(old) : "l"(&g_ticket), "r"(1u) : "memory");
        s_last = (old == (unsigned)(HB - 1)) ? 1u : 0u;
    }
    __syncthreads();
    if (s_last) {
        unsigned cnt = __ldcg(&g_cnt_pad[tid * 32]);
        s_h[tid] = cnt;                   // reuse smem as count table
        __syncthreads();
        unsigned r = 0;
        #pragma unroll 8
        for (int j = 0; j < 256; j++) r += (s_h[j] < cnt) ? 1u : 0u;
        g_packed[tid] = (r << 24) | (unsigned)tid;
        g_cnt_pad[tid * 32] = 0u;
        if (tid == 0) g_ticket = 0u;
    }
}

// ---------------------------------------------------------------------------
// Kernel 2: entropy pool, full-width 14-row strips, u32 priority keys.
// key = rank<<24 | lrow<<18 | col<<10 | value  (disjoint fields).
// Unsigned min over a 3x3 window == argmin by (rank, row, col) == jnp.argmin
// with first-occurrence tie-break (equal counts -> equal rank; position bits
// break ties positionally, never by value). Every compare is ONE umin.
// Phase 1: 2 fixed iterations of 32-byte loads (x L2-resident from hist; rows
//          clamped to H-1 at the image edge -> uniform trip count; clamped
//          rows feed only never-stored outputs). FADD +2^23 bit-trick replaces
//          F2I. 8 table lookups + position-adds -> 2 x STS.128.
// Phase 2: thread = (rg in {0,1} x 7 rows, col pair 2cg,2cg+1). Per row:
//          2 x LDS.64 -> 3 umin (shared middle) for both horizontal 3-mins;
//          rolling vertical: 4 umin per output pair. float2 coalesced stores.
// ---------------------------------------------------------------------------
__global__ void __launch_bounds__(256) pool_kernel(const float* __restrict__ x,
                                                   float* __restrict__ out) {
    __shared__ unsigned s_tbl[256];
    __shared__ unsigned s32[PROWS * WPAD];   // 16,640 B

    const int tid = threadIdx.x;
    s_tbl[tid] = g_packed[tid];
    __syncthreads();

    const int plane = blockIdx.y;
    const int r0 = blockIdx.x * PTH;
    const float* xp = x + (size_t)plane * (H * W);

    #pragma unroll
    for (int it = 0; it < 2; it++) {
        const int u = it * 256 + tid;        // 0..511 (32-byte units)
        const int lr = u >> 5;               // 0..15
        const int c8 = (u & 31) * 8;
        const int gr = min(r0 + lr, H - 1);  // clamp at image edge
        ull u0, u1, u2, u3;
        const ull* p = (const ull*)(xp + gr * W + c8);
        asm volatile("ld.global.nc.v4.b64 {%0,%1,%2,%3}, [%4];"
                     : "=l"(u0), "=l"(u1), "=l"(u2), "=l"(u3) : "l"(p));
        const unsigned pb = ((unsigned)lr << 18) | ((unsigned)c8 << 10);

        #define IDX(w) ((__float_as_uint(__uint_as_float((unsigned)(w)) + 8388608.0f)) & 255u)
        unsigned e0 = s_tbl[IDX(u0)]       + (pb + (0u << 10));
        unsigned e1 = s_tbl[IDX(u0 >> 32)] + (pb + (1u << 10));
        unsigned e2 = s_tbl[IDX(u1)]       + (pb + (2u << 10));
        unsigned e3 = s_tbl[IDX(u1 >> 32)] + (pb + (3u << 10));
        unsigned e4 = s_tbl[IDX(u2)]       + (pb + (4u << 10));
        unsigned e5 = s_tbl[IDX(u2 >> 32)] + (pb + (5u << 10));
        unsigned e6 = s_tbl[IDX(u3)]       + (pb + (6u << 10));
        unsigned e7 = s_tbl[IDX(u3 >> 32)] + (pb + (7u << 10));
        #undef IDX

        unsigned* d = &s32[lr * WPAD + c8];
        *(uint4*)d       = make_uint4(e0, e1, e2, e3);
        *(uint4*)(d + 4) = make_uint4(e4, e5, e6, e7);
    }
    __syncthreads();

    const int cg = tid & 127;        // column pair: cols 2cg, 2cg+1
    const int rg = tid >> 7;         // 0/1 -> out rows 7rg..7rg+6
    const int c0 = 2 * cg;
    const int lr0 = rg * 7;

    if (c0 >= WO) return;            // cg==127: cols 254,255 both invalid

    auto ldrow = [&](int lr, unsigned& m0, unsigned& m1) {
        const unsigned* rp = &s32[lr * WPAD + c0];
        uint2 A = *(const uint2*)rp;        // cols c0, c0+1
        uint2 B = *(const uint2*)(rp + 2);  // cols c0+2, c0+3
        unsigned m01 = min(A.y, B.x);
        m0 = min(A.x, m01);
        m1 = min(m01, B.y);
    };

    unsigned a0, a1, b0, b1, e0, e1;
    ldrow(lr0 + 0, a0, a1);
    ldrow(lr0 + 1, b0, b1);

    float* op = out + (size_t)plane * (HO * WO);
    #pragma unroll
    for (int k = 0; k < 7; k++) {
        const int orow = r0 + lr0 + k;
        if (orow >= HO) break;
        ldrow(lr0 + k + 2, e0, e1);
        unsigned q0 = min(min(a0, b0), e0);
        unsigned q1 = min(min(a1, b1), e1);
        float2 o;
        o.x = (float)(q0 & 255u);
        o.y = (float)(q1 & 255u);
        __stcs((float2*)&op[(size_t)orow * WO + c0], o);
        a0 = b0; a1 = b1; b0 = e0; b1 = e1;
    }
}

// ---------------------------------------------------------------------------
extern "C" void kernel_launch(void* const* d_in, const int* in_sizes, int n_in,
                              void* d_out, int out_size) {
    const float* x = (const float*)d_in[0];
    float* out = (float*)d_out;

    hist_kernel<<<HB, HTH>>>(x);

    dim3 grid((HO + PTH - 1) / PTH, PLANES);   // (19, 256) = 4864 blocks
    pool_kernel<<<grid, 256>>>(x, out);
}